// round 9
// baseline (speedup 1.0000x reference)
#include <cuda_runtime.h>
#include <cstdint>

// Problem dims
#define Bb 384
#define Ss 128
#define Ee 512
#define Hh 4
#define Dd 128
#define Mtot (Bb*Ss)   // 49152

// Scratch (device globals; resolved via cudaGetSymbolAddress)
__device__ float    g_q[(size_t)Mtot*Ee];
__device__ float    g_k[(size_t)Mtot*Ee];
__device__ float    g_v[(size_t)Mtot*Ee];
__device__ uint32_t g_xh[(size_t)Mtot*Ee/2];   // x split hi (bf16x2 words)
__device__ uint32_t g_xl[(size_t)Mtot*Ee/2];   // x split lo
__device__ uint32_t g_ath[(size_t)Mtot*Ee/2];  // att split hi
__device__ uint32_t g_atl[(size_t)Mtot*Ee/2];  // att split lo
__device__ uint32_t g_wth[(size_t)4*Ee*Ee/2];  // W^T hi, 4 mats [N][K]
__device__ uint32_t g_wtl[(size_t)4*Ee*Ee/2];  // W^T lo

// ---------------- PTX helpers ----------------
__device__ __forceinline__ void mma8(float* c, const uint32_t* a, const uint32_t* b) {
    asm volatile(
        "mma.sync.aligned.m16n8k8.row.col.f32.tf32.tf32.f32 "
        "{%0,%1,%2,%3}, {%4,%5,%6,%7}, {%8,%9}, {%0,%1,%2,%3};\n"
        : "+f"(c[0]), "+f"(c[1]), "+f"(c[2]), "+f"(c[3])
        : "r"(a[0]), "r"(a[1]), "r"(a[2]), "r"(a[3]), "r"(b[0]), "r"(b[1]));
}
__device__ __forceinline__ void mma16(float* c, const uint32_t* a, const uint32_t* b) {
    asm volatile(
        "mma.sync.aligned.m16n8k16.row.col.f32.bf16.bf16.f32 "
        "{%0,%1,%2,%3}, {%4,%5,%6,%7}, {%8,%9}, {%0,%1,%2,%3};\n"
        : "+f"(c[0]), "+f"(c[1]), "+f"(c[2]), "+f"(c[3])
        : "r"(a[0]), "r"(a[1]), "r"(a[2]), "r"(a[3]), "r"(b[0]), "r"(b[1]));
}
__device__ __forceinline__ void ldsm_x4(uint32_t* r, uint32_t saddr) {
    asm volatile("ldmatrix.sync.aligned.m8n8.x4.shared.b16 {%0,%1,%2,%3}, [%4];\n"
        : "=r"(r[0]), "=r"(r[1]), "=r"(r[2]), "=r"(r[3]) : "r"(saddr));
}
__device__ __forceinline__ void ldsm_x2(uint32_t* r, uint32_t saddr) {
    asm volatile("ldmatrix.sync.aligned.m8n8.x2.shared.b16 {%0,%1}, [%2];\n"
        : "=r"(r[0]), "=r"(r[1]) : "r"(saddr));
}
__device__ __forceinline__ uint32_t tf32_hi(float x) {
    return __float_as_uint(x) & 0xFFFFE000u;
}
__device__ __forceinline__ uint32_t tf32_lo(float x, uint32_t hi) {
    return __float_as_uint(x - __uint_as_float(hi));
}
// Split (x0,x1) -> packed bf16x2 hi (rn) + packed bf16x2 lo residual.
// x0 in low 16 bits (even k), x1 in high (odd k).
__device__ __forceinline__ void split2(float x0, float x1, uint32_t& hi, uint32_t& lo) {
    asm("cvt.rn.bf16x2.f32 %0, %1, %2;" : "=r"(hi) : "f"(x1), "f"(x0));
    float r0 = x0 - __uint_as_float(hi << 16);
    float r1 = x1 - __uint_as_float(hi & 0xFFFF0000u);
    asm("cvt.rn.bf16x2.f32 %0, %1, %2;" : "=r"(lo) : "f"(r1), "f"(r0));
}
__device__ __forceinline__ void cpasync16(void* dst, const void* src) {
    uint32_t s = (uint32_t)__cvta_generic_to_shared(dst);
    asm volatile("cp.async.cg.shared.global [%0], [%1], 16;\n" :: "r"(s), "l"(src));
}

// ---------------- Prepass: fp32 -> bf16 hi/lo ----------------
__global__ __launch_bounds__(256) void conv_x(const float* __restrict__ x,
                                              uint32_t* __restrict__ xh,
                                              uint32_t* __restrict__ xl) {
    size_t i = (size_t)blockIdx.x * 256 + threadIdx.x;   // < Mtot*Ee/2
    float2 v = ((const float2*)x)[i];
    uint32_t h, l; split2(v.x, v.y, h, l);
    xh[i] = h; xl[i] = l;
}

// W [K][N] -> W^T hi/lo [N][K] (bf16x2 words along K)
__global__ __launch_bounds__(256) void conv_w(const float* __restrict__ W,
                                              uint32_t* __restrict__ wh,
                                              uint32_t* __restrict__ wl) {
    int i = blockIdx.x * 256 + threadIdx.x;   // < Ee*Ee/2
    int kw = i & (Ee/2 - 1), n = i >> 8;      // Ee/2 = 256
    float a = W[(size_t)(2*kw  )*Ee + n];
    float b = W[(size_t)(2*kw+1)*Ee + n];
    uint32_t h, l; split2(a, b, h, l);
    wh[(size_t)n*(Ee/2) + kw] = h;
    wl[(size_t)n*(Ee/2) + kw] = l;
}

// ---------------- Pure-bf16 GEMM ----------------
// C[M,N] = A[M,K] @ B^T[N,K]^T + bias, with A,B pre-split bf16 hi/lo.
// Block 128x128, BK=32, 2-stage cp.async, 8 warps (4x2), warp 32x64,
// 3xBF16-split: AH*BH + AH*BL + AL*BH.
#define LDHW 20               // tile row stride in words (40 bf16, conflict-free)
#define TILEW (128*LDHW)      // 2560 words per tile
#define STGW  (4*TILEW)       // Ah|Al|Bh|Bl per stage = 10240 words = 40KB
#define GEMM_SMEM (2*STGW*4)  // 81920 bytes

__device__ __forceinline__ void bgemm_body(const uint16_t* __restrict__ Ah16,
                                           const uint16_t* __restrict__ Al16,
                                           const uint16_t* __restrict__ Bh16,
                                           const uint16_t* __restrict__ Bl16,
                                           const float* __restrict__ bias,
                                           float* __restrict__ C,
                                           int bm, int bn, uint32_t* smw) {
    const int tid  = threadIdx.x;
    const int warp = tid >> 5;
    const int lane = tid & 31;
    const int g = lane >> 2, t = lane & 3;
    const int wm = (warp >> 1) * 32;
    const int wn = (warp & 1) * 64;

    // cp.async coords: 2048 16B-chunks/stage, 8 per thread
    const int cr = tid >> 2;            // 0..63 (+64*it)
    const int cc = (tid & 3) << 3;      // k elem offset 0,8,16,24

    // ldmatrix lane->row/col
    const int arow = lane & 15;
    const int acol = ((lane >> 4) & 1) * 8;
    const int brow = lane & 7;
    const int bcol = ((lane >> 3) & 1) * 8;

    const uint32_t smb = (uint32_t)__cvta_generic_to_shared(smw);

    float acc[2][8][4] = {};

    #define ISSUE(k0, s)  do {                                                    \
        uint32_t* st = smw + (s)*STGW;                                            \
        _Pragma("unroll")                                                         \
        for (int it = 0; it < 2; it++) {                                          \
            int r = cr + it*64;                                                   \
            int dof = r*LDHW + (cc >> 1);                                         \
            cpasync16(st + 0*TILEW + dof, Ah16 + (size_t)(bm + r)*Ee + (k0) + cc);\
            cpasync16(st + 1*TILEW + dof, Al16 + (size_t)(bm + r)*Ee + (k0) + cc);\
            cpasync16(st + 2*TILEW + dof, Bh16 + (size_t)(bn + r)*Ee + (k0) + cc);\
            cpasync16(st + 3*TILEW + dof, Bl16 + (size_t)(bn + r)*Ee + (k0) + cc);\
        }                                                                         \
        asm volatile("cp.async.commit_group;\n");                                 \
    } while (0)

    ISSUE(0, 0);

    for (int ki = 0; ki < Ee/32; ki++) {
        if (ki + 1 < Ee/32) {
            ISSUE((ki+1)*32, (ki+1) & 1);
            asm volatile("cp.async.wait_group 1;\n");
        } else {
            asm volatile("cp.async.wait_group 0;\n");
        }
        __syncthreads();

        const uint32_t base = smb + (uint32_t)((ki & 1)*STGW*4);

        #pragma unroll
        for (int kk = 0; kk < 32; kk += 16) {
            uint32_t AH[2][4], AL[2][4];
            #pragma unroll
            for (int i = 0; i < 2; i++) {
                uint32_t off = (uint32_t)(((wm + i*16 + arow)*40 + kk + acol) * 2);
                ldsm_x4(AH[i], base + 0*TILEW*4 + off);
                ldsm_x4(AL[i], base + 1*TILEW*4 + off);
            }
            #pragma unroll
            for (int j = 0; j < 8; j++) {
                uint32_t BH[2], BL[2];
                uint32_t off = (uint32_t)(((wn + j*8 + brow)*40 + kk + bcol) * 2);
                ldsm_x2(BH, base + 2*TILEW*4 + off);
                ldsm_x2(BL, base + 3*TILEW*4 + off);
                #pragma unroll
                for (int i = 0; i < 2; i++) {
                    mma16(acc[i][j], AH[i], BH);
                    mma16(acc[i][j], AH[i], BL);
                    mma16(acc[i][j], AL[i], BH);
                }
            }
        }
        __syncthreads();   // protect stage reuse before next ISSUE
    }
    #undef ISSUE

    // Epilogue: fragment stores + bias
    #pragma unroll
    for (int i = 0; i < 2; i++) {
        #pragma unroll
        for (int j = 0; j < 8; j++) {
            int row = bm + wm + i*16 + g;
            int col = bn + wn + j*8 + 2*t;
            float bz0 = bias[col], bz1 = bias[col+1];
            float2 v0 = { acc[i][j][0] + bz0, acc[i][j][1] + bz1 };
            float2 v1 = { acc[i][j][2] + bz0, acc[i][j][3] + bz1 };
            *(float2*)(C + (size_t)row*Ee + col)       = v0;
            *(float2*)(C + (size_t)(row + 8)*Ee + col) = v1;
        }
    }
}

// Fused QKV: grid (12, 384); mat = x%3, N-tile = x/3
__global__ __launch_bounds__(256, 2) void qkv_kernel(
        const uint16_t* __restrict__ xh, const uint16_t* __restrict__ xl,
        const uint16_t* __restrict__ wth, const uint16_t* __restrict__ wtl,
        const float* __restrict__ bq, const float* __restrict__ bk,
        const float* __restrict__ bv,
        float* __restrict__ q, float* __restrict__ k, float* __restrict__ v) {
    extern __shared__ uint32_t smw[];
    const int mat = blockIdx.x % 3;
    const int bn  = (blockIdx.x / 3) * 128;
    const int bm  = blockIdx.y * 128;
    const uint16_t* Bh = wth + (size_t)mat*Ee*Ee;
    const uint16_t* Bl = wtl + (size_t)mat*Ee*Ee;
    const float* bias; float* C;
    if (mat == 0)      { bias = bq; C = q; }
    else if (mat == 1) { bias = bk; C = k; }
    else               { bias = bv; C = v; }
    bgemm_body(xh, xl, Bh, Bl, bias, C, bm, bn, smw);
}

__global__ __launch_bounds__(256, 2) void out_kernel(
        const uint16_t* __restrict__ ath, const uint16_t* __restrict__ atl,
        const uint16_t* __restrict__ wth, const uint16_t* __restrict__ wtl,
        const float* __restrict__ bo, float* __restrict__ y) {
    extern __shared__ uint32_t smw[];
    bgemm_body(ath, atl, wth + (size_t)3*Ee*Ee, wtl + (size_t)3*Ee*Ee,
               bo, y, blockIdx.y * 128, blockIdx.x * 128, smw);
}

// ---------------- Attention (R7-proven; epilogue now writes bf16 hi/lo) ----
#define LDT 132  // Dd + 4

__global__ __launch_bounds__(256) void attn_kernel(const float* __restrict__ gq,
                                                   const float* __restrict__ gk,
                                                   const float* __restrict__ gv,
                                                   uint32_t* __restrict__ ath,
                                                   uint32_t* __restrict__ atl) {
    extern __shared__ float sm[];
    float* sQ = sm;                    // [128][LDT]  (reused for V)
    float* sK = sm + Ss*LDT;
    float* sS = sm + 2*Ss*LDT;

    const int bh = blockIdx.x;
    const int b  = bh >> 2;
    const int h  = bh & 3;
    const int tid  = threadIdx.x;
    const int warp = tid >> 5;
    const int lane = tid & 31;
    const int g = lane >> 2, t = lane & 3;

    const float* qbase = gq + (size_t)b*Ss*Ee + h*Dd;
    const float* kbase = gk + (size_t)b*Ss*Ee + h*Dd;
    const float* vbase = gv + (size_t)b*Ss*Ee + h*Dd;

    #pragma unroll
    for (int it = 0; it < 16; it++) {
        int idx = tid + it*256;
        int r = idx >> 5, c = (idx & 31) << 2;
        float4 v = *(const float4*)(qbase + (size_t)r*Ee + c);
        float* d = sQ + r*LDT + c;
        d[0]=v.x; d[1]=v.y; d[2]=v.z; d[3]=v.w;
        v = *(const float4*)(kbase + (size_t)r*Ee + c);
        d = sK + r*LDT + c;
        d[0]=v.x; d[1]=v.y; d[2]=v.z; d[3]=v.w;
    }
    __syncthreads();

    float acc[16][4];

    #pragma unroll
    for (int j = 0; j < 16; j++) { acc[j][0]=0.f; acc[j][1]=0.f; acc[j][2]=0.f; acc[j][3]=0.f; }

    for (int kk = 0; kk < Dd; kk += 8) {
        const float* p = sQ + (warp*16 + g)*LDT + kk + t;
        float a0 = p[0], a1 = p[8*LDT], a2 = p[4], a3 = p[8*LDT+4];
        uint32_t ah[4] = { tf32_hi(a0), tf32_hi(a1), tf32_hi(a2), tf32_hi(a3) };
        uint32_t al[4] = { tf32_lo(a0, ah[0]), tf32_lo(a1, ah[1]),
                           tf32_lo(a2, ah[2]), tf32_lo(a3, ah[3]) };
        #pragma unroll
        for (int j = 0; j < 16; j++) {
            const float* q = sK + (j*8 + g)*LDT + kk + t;
            float b0 = q[0], b1 = q[4];
            uint32_t bh[2] = { tf32_hi(b0), tf32_hi(b1) };
            uint32_t bl[2] = { tf32_lo(b0, bh[0]), tf32_lo(b1, bh[1]) };
            mma8(acc[j], ah, bh);
            mma8(acc[j], ah, bl);
            mma8(acc[j], al, bh);
        }
    }
    #pragma unroll
    for (int j = 0; j < 16; j++) {
        float* p = sS + (warp*16 + g)*LDT + j*8 + 2*t;
        *(float2*)p              = { acc[j][0], acc[j][1] };
        *(float2*)(p + 8*LDT)    = { acc[j][2], acc[j][3] };
    }
    __syncthreads();

    float* sV = sQ;
    #pragma unroll
    for (int it = 0; it < 16; it++) {
        int idx = tid + it*256;
        int r = idx >> 5, c = (idx & 31) << 2;
        float4 v = *(const float4*)(vbase + (size_t)r*Ee + c);
        float* d = sV + r*LDT + c;
        d[0]=v.x; d[1]=v.y; d[2]=v.z; d[3]=v.w;
    }

    #pragma unroll 1
    for (int rr = 0; rr < 16; rr++) {
        float* row = sS + (warp*16 + rr)*LDT;
        float v0 = row[lane], v1 = row[lane+32], v2 = row[lane+64], v3 = row[lane+96];
        float m = fmaxf(fmaxf(v0, v1), fmaxf(v2, v3));
        #pragma unroll
        for (int off = 16; off > 0; off >>= 1)
            m = fmaxf(m, __shfl_xor_sync(0xFFFFFFFFu, m, off));
        v0 = __expf(v0 - m); v1 = __expf(v1 - m); v2 = __expf(v2 - m); v3 = __expf(v3 - m);
        float s = v0 + v1 + v2 + v3;
        #pragma unroll
        for (int off = 16; off > 0; off >>= 1)
            s += __shfl_xor_sync(0xFFFFFFFFu, s, off);
        float inv = 1.0f / s;
        row[lane]    = v0 * inv;
        row[lane+32] = v1 * inv;
        row[lane+64] = v2 * inv;
        row[lane+96] = v3 * inv;
    }
    __syncthreads();

    #pragma unroll
    for (int j = 0; j < 16; j++) { acc[j][0]=0.f; acc[j][1]=0.f; acc[j][2]=0.f; acc[j][3]=0.f; }

    for (int kk = 0; kk < Ss; kk += 8) {
        const float* p = sS + (warp*16 + g)*LDT + kk + t;
        float a0 = p[0], a1 = p[8*LDT], a2 = p[4], a3 = p[8*LDT+4];
        uint32_t ah[4] = { tf32_hi(a0), tf32_hi(a1), tf32_hi(a2), tf32_hi(a3) };
        uint32_t al[4] = { tf32_lo(a0, ah[0]), tf32_lo(a1, ah[1]),
                           tf32_lo(a2, ah[2]), tf32_lo(a3, ah[3]) };
        #pragma unroll
        for (int j = 0; j < 16; j++) {
            const float* q = sV + (kk + t)*LDT + j*8 + g;
            float b0 = q[0], b1 = q[4*LDT];
            uint32_t bh[2] = { tf32_hi(b0), tf32_hi(b1) };
            uint32_t bl[2] = { tf32_lo(b0, bh[0]), tf32_lo(b1, bh[1]) };
            mma8(acc[j], ah, bh);
            mma8(acc[j], ah, bl);
            mma8(acc[j], al, bh);
        }
    }

    // Epilogue: split fp32 accumulators -> bf16 hi/lo att (exact; no extra pass)
    #pragma unroll
    for (int j = 0; j < 16; j++) {
        size_t row = (size_t)(b*Ss + warp*16 + g);
        int colw = h*(Dd/2) + j*4 + t;     // word index: (h*128 + j*8 + 2t)/2
        uint32_t h0, l0, h1, l1;
        split2(acc[j][0], acc[j][1], h0, l0);
        split2(acc[j][2], acc[j][3], h1, l1);
        ath[row*(Ee/2) + colw]       = h0;
        atl[row*(Ee/2) + colw]       = l0;
        ath[(row + 8)*(Ee/2) + colw] = h1;
        atl[(row + 8)*(Ee/2) + colw] = l1;
    }
}

// ---------------- Launch ----------------
extern "C" void kernel_launch(void* const* d_in, const int* in_sizes, int n_in,
                              void* d_out, int out_size) {
    const float* x  = (const float*)d_in[0];
    const float* Wq = (const float*)d_in[1];
    const float* bq = (const float*)d_in[2];
    const float* Wk = (const float*)d_in[3];
    const float* bk = (const float*)d_in[4];
    const float* Wv = (const float*)d_in[5];
    const float* bv = (const float*)d_in[6];
    const float* Wo = (const float*)d_in[7];
    const float* bo = (const float*)d_in[8];
    float* y = (float*)d_out;

    float *q, *k, *v;
    uint32_t *xh, *xl, *ath, *atl, *wth, *wtl;
    cudaGetSymbolAddress((void**)&q,   g_q);
    cudaGetSymbolAddress((void**)&k,   g_k);
    cudaGetSymbolAddress((void**)&v,   g_v);
    cudaGetSymbolAddress((void**)&xh,  g_xh);
    cudaGetSymbolAddress((void**)&xl,  g_xl);
    cudaGetSymbolAddress((void**)&ath, g_ath);
    cudaGetSymbolAddress((void**)&atl, g_atl);
    cudaGetSymbolAddress((void**)&wth, g_wth);
    cudaGetSymbolAddress((void**)&wtl, g_wtl);

    const int attn_smem = 3 * Ss * LDT * (int)sizeof(float);   // 202752 bytes
    cudaFuncSetAttribute(attn_kernel, cudaFuncAttributeMaxDynamicSharedMemorySize, attn_smem);
    cudaFuncSetAttribute(qkv_kernel,  cudaFuncAttributeMaxDynamicSharedMemorySize, GEMM_SMEM);
    cudaFuncSetAttribute(out_kernel,  cudaFuncAttributeMaxDynamicSharedMemorySize, GEMM_SMEM);

    // Prepass: split x and W^T once
    conv_x<<<Mtot*Ee/2/256, 256>>>(x, xh, xl);
    conv_w<<<Ee*Ee/2/256, 256>>>(Wq, wth + 0*(size_t)Ee*Ee/2, wtl + 0*(size_t)Ee*Ee/2);
    conv_w<<<Ee*Ee/2/256, 256>>>(Wk, wth + 1*(size_t)Ee*Ee/2, wtl + 1*(size_t)Ee*Ee/2);
    conv_w<<<Ee*Ee/2/256, 256>>>(Wv, wth + 2*(size_t)Ee*Ee/2, wtl + 2*(size_t)Ee*Ee/2);
    conv_w<<<Ee*Ee/2/256, 256>>>(Wo, wth + 3*(size_t)Ee*Ee/2, wtl + 3*(size_t)Ee*Ee/2);

    dim3 gqkv(12, Mtot/128);
    qkv_kernel<<<gqkv, 256, GEMM_SMEM>>>((const uint16_t*)xh, (const uint16_t*)xl,
                                         (const uint16_t*)wth, (const uint16_t*)wtl,
                                         bq, bk, bv, q, k, v);

    attn_kernel<<<Bb*Hh, 256, attn_smem>>>(q, k, v, ath, atl);

    dim3 gout(Ee/128, Mtot/128);
    out_kernel<<<gout, 256, GEMM_SMEM>>>((const uint16_t*)ath, (const uint16_t*)atl,
                                         (const uint16_t*)wth, (const uint16_t*)wtl,
                                         bo, y);
}

// round 12
// speedup vs baseline: 1.1613x; 1.1613x over previous
#include <cuda_runtime.h>
#include <cstdint>

// Problem dims
#define Bb 384
#define Ss 128
#define Ee 512
#define Hh 4
#define Dd 128
#define Mtot (Bb*Ss)   // 49152

// Scratch (device globals; resolved via cudaGetSymbolAddress)
__device__ uint32_t g_qh[(size_t)Mtot*Ee/2];
__device__ uint32_t g_ql[(size_t)Mtot*Ee/2];
__device__ uint32_t g_kh[(size_t)Mtot*Ee/2];
__device__ uint32_t g_kl[(size_t)Mtot*Ee/2];
__device__ uint32_t g_vh[(size_t)Mtot*Ee/2];
__device__ uint32_t g_vl[(size_t)Mtot*Ee/2];
__device__ uint32_t g_ath[(size_t)Mtot*Ee/2];
__device__ uint32_t g_atl[(size_t)Mtot*Ee/2];
__device__ uint32_t g_wthO[(size_t)Ee*Ee/2];  // Wo^T hi [N][K]
__device__ uint32_t g_wtlO[(size_t)Ee*Ee/2];  // Wo^T lo

// ---------------- PTX helpers ----------------
__device__ __forceinline__ void mma16(float* c, const uint32_t* a, const uint32_t* b) {
    asm volatile(
        "mma.sync.aligned.m16n8k16.row.col.f32.bf16.bf16.f32 "
        "{%0,%1,%2,%3}, {%4,%5,%6,%7}, {%8,%9}, {%0,%1,%2,%3};\n"
        : "+f"(c[0]), "+f"(c[1]), "+f"(c[2]), "+f"(c[3])
        : "r"(a[0]), "r"(a[1]), "r"(a[2]), "r"(a[3]), "r"(b[0]), "r"(b[1]));
}
__device__ __forceinline__ void ldsm_x4(uint32_t* r, uint32_t saddr) {
    asm volatile("ldmatrix.sync.aligned.m8n8.x4.shared.b16 {%0,%1,%2,%3}, [%4];\n"
        : "=r"(r[0]), "=r"(r[1]), "=r"(r[2]), "=r"(r[3]) : "r"(saddr));
}
__device__ __forceinline__ void ldsm_x2(uint32_t* r, uint32_t saddr) {
    asm volatile("ldmatrix.sync.aligned.m8n8.x2.shared.b16 {%0,%1}, [%2];\n"
        : "=r"(r[0]), "=r"(r[1]) : "r"(saddr));
}
__device__ __forceinline__ void ldsm_x2t(uint32_t* r, uint32_t saddr) {
    asm volatile("ldmatrix.sync.aligned.m8n8.x2.trans.shared.b16 {%0,%1}, [%2];\n"
        : "=r"(r[0]), "=r"(r[1]) : "r"(saddr));
}
// Split (x0,x1) -> packed bf16x2 hi (rn) + packed bf16x2 lo residual.
// x0 in low 16 bits (even col), x1 in high (odd col).
__device__ __forceinline__ void split2(float x0, float x1, uint32_t& hi, uint32_t& lo) {
    asm("cvt.rn.bf16x2.f32 %0, %1, %2;" : "=r"(hi) : "f"(x1), "f"(x0));
    float r0 = x0 - __uint_as_float(hi << 16);
    float r1 = x1 - __uint_as_float(hi & 0xFFFF0000u);
    asm("cvt.rn.bf16x2.f32 %0, %1, %2;" : "=r"(lo) : "f"(r1), "f"(r0));
}
__device__ __forceinline__ uint32_t smem_u32(const void* p) {
    return (uint32_t)__cvta_generic_to_shared(p);
}
__device__ __forceinline__ void cpasync16(uint32_t dst_smem, const void* src) {
    asm volatile("cp.async.cg.shared.global [%0], [%1], 16;\n" :: "r"(dst_smem), "l"(src));
}

// ---------------- Prepass: Wo [K][N] -> Wo^T hi/lo [N][K], coalesced ----------------
__global__ __launch_bounds__(256) void conv_w(const float* __restrict__ W,
                                              uint32_t* __restrict__ wh,
                                              uint32_t* __restrict__ wl) {
    __shared__ uint32_t sh[32][33], sl[32][33];
    const int tx = threadIdx.x, ty = threadIdx.y;
    const int n0 = blockIdx.x * 32, kw0 = blockIdx.y * 32;
    #pragma unroll
    for (int dy = 0; dy < 32; dy += 8) {
        int kw = kw0 + ty + dy;
        float a = W[(size_t)(2*kw  )*Ee + n0 + tx];
        float b = W[(size_t)(2*kw+1)*Ee + n0 + tx];
        uint32_t h, l; split2(a, b, h, l);
        sh[ty+dy][tx] = h; sl[ty+dy][tx] = l;
    }
    __syncthreads();
    #pragma unroll
    for (int dy = 0; dy < 32; dy += 8) {
        int n = n0 + ty + dy;
        wh[(size_t)n*(Ee/2) + kw0 + tx] = sh[tx][ty+dy];
        wl[(size_t)n*(Ee/2) + kw0 + tx] = sl[tx][ty+dy];
    }
}

// =========== QKV GEMM (R7-proven mainloop; epilogue writes bf16 hi/lo) ===========
#define LDA 36
#define LDB 132
#define ASTG (128*LDA)
#define WSTG (32*LDB)
#define LDH  20
#define HTW  (128*LDH)
#define AHIW (2*ASTG + 2*WSTG)
#define ALOW (AHIW + HTW)
#define WTHI (ALOW + HTW)
#define WTLO (WTHI + HTW)
#define GEMM_SMEM ((WTLO + HTW) * 4)   // 111616 bytes

__device__ __forceinline__ void gemm_body(const float* __restrict__ A,
                                          const float* __restrict__ W,
                                          const float* __restrict__ bias,
                                          uint32_t* __restrict__ Ch,
                                          uint32_t* __restrict__ Cl,
                                          int bm, int bn, float* smem) {
    float* Asm = smem;
    float* Wsm = smem + 2*ASTG;
    uint32_t* ah_w = (uint32_t*)(smem + AHIW);
    uint32_t* al_w = (uint32_t*)(smem + ALOW);
    uint32_t* wh_w = (uint32_t*)(smem + WTHI);
    uint32_t* wl_w = (uint32_t*)(smem + WTLO);

    const int tid  = threadIdx.x;
    const int warp = tid >> 5;
    const int lane = tid & 31;
    const int g = lane >> 2, t = lane & 3;
    const int wm = (warp >> 1) * 32;
    const int wn = (warp & 1) * 64;

    const int ar = tid >> 3, ac = (tid & 7) << 2;
    const int wr = tid >> 5, wc = (tid & 31) << 2;

    const int arow = lane & 15;
    const int acol = ((lane >> 4) & 1) * 8;
    const int brow = lane & 7;
    const int bcol = ((lane >> 3) & 1) * 8;

    const uint32_t ah_b = smem_u32(ah_w);
    const uint32_t al_b = smem_u32(al_w);
    const uint32_t wh_b = smem_u32(wh_w);
    const uint32_t wl_b = smem_u32(wl_w);

    float acc[2][8][4] = {};

    #define ISSUE(k0, s)  do {                                                  \
        float* as_ = Asm + (s)*ASTG;                                            \
        float* ws_ = Wsm + (s)*WSTG;                                            \
        _Pragma("unroll")                                                       \
        for (int it = 0; it < 4; it++)                                          \
            cpasync16(smem_u32(as_ + (ar + it*32)*LDA + ac),                    \
                      A + (size_t)(bm + ar + it*32)*Ee + (k0) + ac);            \
        _Pragma("unroll")                                                       \
        for (int it = 0; it < 4; it++)                                          \
            cpasync16(smem_u32(ws_ + (wr + it*8)*LDB + wc),                     \
                      W + (size_t)((k0) + wr + it*8)*Ee + bn + wc);             \
        asm volatile("cp.async.commit_group;\n");                               \
    } while (0)

    ISSUE(0, 0);

    for (int ki = 0; ki < Ee/32; ki++) {
        if (ki + 1 < Ee/32) {
            ISSUE((ki+1)*32, (ki+1) & 1);
            asm volatile("cp.async.wait_group 1;\n");
        } else {
            asm volatile("cp.async.wait_group 0;\n");
        }
        __syncthreads();

        const float* as_ = Asm + (ki & 1)*ASTG;
        const float* ws_ = Wsm + (ki & 1)*WSTG;

        // convert A tile fp32 -> bf16 hi/lo
        #pragma unroll
        for (int it = 0; it < 4; it++) {
            int r = ar + it*32;
            float4 v = *(const float4*)(as_ + r*LDA + ac);
            uint32_t h0, l0, h1, l1;
            split2(v.x, v.y, h0, l0);
            split2(v.z, v.w, h1, l1);
            int o = r*LDH + (ac >> 1);
            ah_w[o] = h0; ah_w[o+1] = h1;
            al_w[o] = l0; al_w[o+1] = l1;
        }
        // convert W tile fp32 [k][n] -> transposed bf16 hi/lo [n][k]
        #pragma unroll
        for (int it = 0; it < 4; it++) {
            int unit = tid + it*256;
            int n = unit & 127, k0 = (unit >> 7) << 2;
            float c0 = ws_[(k0  )*LDB + n];
            float c1 = ws_[(k0+1)*LDB + n];
            float c2 = ws_[(k0+2)*LDB + n];
            float c3 = ws_[(k0+3)*LDB + n];
            uint32_t h0, l0, h1, l1;
            split2(c0, c1, h0, l0);
            split2(c2, c3, h1, l1);
            int o = n*LDH + (k0 >> 1);
            wh_w[o] = h0; wh_w[o+1] = h1;
            wl_w[o] = l0; wl_w[o+1] = l1;
        }
        __syncthreads();

        #pragma unroll
        for (int kk = 0; kk < 32; kk += 16) {
            uint32_t AH[2][4], AL[2][4];
            #pragma unroll
            for (int i = 0; i < 2; i++) {
                uint32_t off = (uint32_t)(((wm + i*16 + arow)*40 + kk + acol) * 2);
                ldsm_x4(AH[i], ah_b + off);
                ldsm_x4(AL[i], al_b + off);
            }
            #pragma unroll
            for (int j = 0; j < 8; j++) {
                uint32_t BH[2], BL[2];
                uint32_t off = (uint32_t)(((wn + j*8 + brow)*40 + kk + bcol) * 2);
                ldsm_x2(BH, wh_b + off);
                ldsm_x2(BL, wl_b + off);
                #pragma unroll
                for (int i = 0; i < 2; i++) {
                    mma16(acc[i][j], AH[i], BH);
                    mma16(acc[i][j], AH[i], BL);
                    mma16(acc[i][j], AL[i], BH);
                }
            }
        }
    }
    #undef ISSUE

    // Epilogue: bias + exact split -> bf16 hi/lo outputs
    #pragma unroll
    for (int i = 0; i < 2; i++) {
        #pragma unroll
        for (int j = 0; j < 8; j++) {
            int row  = bm + wm + i*16 + g;
            int col  = bn + wn + j*8 + 2*t;
            int colw = col >> 1;
            float bz0 = bias[col], bz1 = bias[col+1];
            uint32_t h0, l0, h1, l1;
            split2(acc[i][j][0] + bz0, acc[i][j][1] + bz1, h0, l0);
            split2(acc[i][j][2] + bz0, acc[i][j][3] + bz1, h1, l1);
            Ch[(size_t)row*(Ee/2) + colw]       = h0;
            Cl[(size_t)row*(Ee/2) + colw]       = l0;
            Ch[(size_t)(row + 8)*(Ee/2) + colw] = h1;
            Cl[(size_t)(row + 8)*(Ee/2) + colw] = l1;
        }
    }
}

__global__ __launch_bounds__(256, 2) void qkv_kernel(const float* __restrict__ x,
        const float* __restrict__ Wq, const float* __restrict__ bq,
        const float* __restrict__ Wk, const float* __restrict__ bk,
        const float* __restrict__ Wv, const float* __restrict__ bv,
        uint32_t* __restrict__ qh, uint32_t* __restrict__ ql,
        uint32_t* __restrict__ kh, uint32_t* __restrict__ kl,
        uint32_t* __restrict__ vh, uint32_t* __restrict__ vl) {
    extern __shared__ float smem[];
    const int mat = blockIdx.x % 3;
    const int bn  = (blockIdx.x / 3) * 128;
    const int bm  = blockIdx.y * 128;
    const float* W; const float* bias; uint32_t* Ch; uint32_t* Cl;
    if (mat == 0)      { W = Wq; bias = bq; Ch = qh; Cl = ql; }
    else if (mat == 1) { W = Wk; bias = bk; Ch = kh; Cl = kl; }
    else               { W = Wv; bias = bv; Ch = vh; Cl = vl; }
    gemm_body(x, W, bias, Ch, Cl, bm, bn, smem);
}

// =========== Output GEMM (R9-validated pure-bf16 bgemm; fp32 C out) ===========
#define LDHW 20
#define TILEW (128*LDHW)
#define STGW  (4*TILEW)
#define BGEMM_SMEM (2*STGW*4)   // 81920 bytes

__global__ __launch_bounds__(256, 2) void out_kernel(
        const uint16_t* __restrict__ Ah16, const uint16_t* __restrict__ Al16,
        const uint16_t* __restrict__ Bh16, const uint16_t* __restrict__ Bl16,
        const float* __restrict__ bias, float* __restrict__ C) {
    extern __shared__ uint32_t smw[];
    const int bm = blockIdx.y * 128;
    const int bn = blockIdx.x * 128;

    const int tid  = threadIdx.x;
    const int warp = tid >> 5;
    const int lane = tid & 31;
    const int g = lane >> 2, t = lane & 3;
    const int wm = (warp >> 1) * 32;
    const int wn = (warp & 1) * 64;

    const int cr = tid >> 2;
    const int cc = (tid & 3) << 3;

    const int arow = lane & 15;
    const int acol = ((lane >> 4) & 1) * 8;
    const int brow = lane & 7;
    const int bcol = ((lane >> 3) & 1) * 8;

    const uint32_t smb = smem_u32(smw);

    float acc[2][8][4] = {};

    #define OISSUE(k0, s)  do {                                                   \
        uint32_t* st = smw + (s)*STGW;                                            \
        _Pragma("unroll")                                                         \
        for (int it = 0; it < 2; it++) {                                          \
            int r = cr + it*64;                                                   \
            int dof = r*LDHW + (cc >> 1);                                         \
            cpasync16(smem_u32(st + 0*TILEW + dof), Ah16 + (size_t)(bm + r)*Ee + (k0) + cc);\
            cpasync16(smem_u32(st + 1*TILEW + dof), Al16 + (size_t)(bm + r)*Ee + (k0) + cc);\
            cpasync16(smem_u32(st + 2*TILEW + dof), Bh16 + (size_t)(bn + r)*Ee + (k0) + cc);\
            cpasync16(smem_u32(st + 3*TILEW + dof), Bl16 + (size_t)(bn + r)*Ee + (k0) + cc);\
        }                                                                         \
        asm volatile("cp.async.commit_group;\n");                                 \
    } while (0)

    OISSUE(0, 0);

    for (int ki = 0; ki < Ee/32; ki++) {
        if (ki + 1 < Ee/32) {
            OISSUE((ki+1)*32, (ki+1) & 1);
            asm volatile("cp.async.wait_group 1;\n");
        } else {
            asm volatile("cp.async.wait_group 0;\n");
        }
        __syncthreads();

        const uint32_t base = smb + (uint32_t)((ki & 1)*STGW*4);

        #pragma unroll
        for (int kk = 0; kk < 32; kk += 16) {
            uint32_t AH[2][4], AL[2][4];
            #pragma unroll
            for (int i = 0; i < 2; i++) {
                uint32_t off = (uint32_t)(((wm + i*16 + arow)*40 + kk + acol) * 2);
                ldsm_x4(AH[i], base + 0*TILEW*4 + off);
                ldsm_x4(AL[i], base + 1*TILEW*4 + off);
            }
            #pragma unroll
            for (int j = 0; j < 8; j++) {
                uint32_t BH[2], BL[2];
                uint32_t off = (uint32_t)(((wn + j*8 + brow)*40 + kk + bcol) * 2);
                ldsm_x2(BH, base + 2*TILEW*4 + off);
                ldsm_x2(BL, base + 3*TILEW*4 + off);
                #pragma unroll
                for (int i = 0; i < 2; i++) {
                    mma16(acc[i][j], AH[i], BH);
                    mma16(acc[i][j], AH[i], BL);
                    mma16(acc[i][j], AL[i], BH);
                }
            }
        }
        __syncthreads();
    }
    #undef OISSUE

    #pragma unroll
    for (int i = 0; i < 2; i++) {
        #pragma unroll
        for (int j = 0; j < 8; j++) {
            int row = bm + wm + i*16 + g;
            int col = bn + wn + j*8 + 2*t;
            float bz0 = bias[col], bz1 = bias[col+1];
            float2 v0 = { acc[i][j][0] + bz0, acc[i][j][1] + bz1 };
            float2 v1 = { acc[i][j][2] + bz0, acc[i][j][3] + bz1 };
            *(float2*)(C + (size_t)row*Ee + col)       = v0;
            *(float2*)(C + (size_t)(row + 8)*Ee + col) = v1;
        }
    }
}

// =========== Attention: bf16-split m16n8k16, one block per (b,h) ===========
// smem: Qh|Ql|Kh|Kl bf16 tiles [128][136] (Q* reused for V*, K* reused for P*),
// then fp32 scores [128][132].
#define LDS2 136                       // halfs per row (272B: conflict-free)
#define T2B  (128*LDS2*2)              // 34816 bytes per bf16 tile
#define OFF_QH 0
#define OFF_QL (T2B)
#define OFF_KH (2*T2B)
#define OFF_KL (3*T2B)
#define OFF_S  (4*T2B)                 // 139264
#define LDT 132
#define ATTN_SMEM (OFF_S + 128*LDT*4)  // 206848 bytes

__global__ __launch_bounds__(256) void attn_kernel(
        const uint16_t* __restrict__ qh, const uint16_t* __restrict__ ql,
        const uint16_t* __restrict__ kh, const uint16_t* __restrict__ kl,
        const uint16_t* __restrict__ vh, const uint16_t* __restrict__ vl,
        uint32_t* __restrict__ ath, uint32_t* __restrict__ atl) {
    extern __shared__ char sm[];
    const uint32_t smb = smem_u32(sm);
    float*    sS   = (float*)(sm + OFF_S);
    uint32_t* sPh  = (uint32_t*)(sm + OFF_KH);   // P hi words (reuses Kh)
    uint32_t* sPl  = (uint32_t*)(sm + OFF_KL);

    const int bh = blockIdx.x;
    const int b  = bh >> 2;
    const int h  = bh & 3;
    const int tid  = threadIdx.x;
    const int warp = tid >> 5;
    const int lane = tid & 31;
    const int g = lane >> 2, t = lane & 3;

    const size_t base = (size_t)(b*Ss)*Ee + h*Dd;   // halfs

    // Load Qh/Ql/Kh/Kl via cp.async: 4 tiles x 2048 16B-chunks
    {
        const uint16_t* srcs[4] = { qh, ql, kh, kl };
        #pragma unroll
        for (int tile = 0; tile < 4; tile++) {
            const uint16_t* s = srcs[tile] + base;
            uint32_t dstb = smb + tile*T2B;
            #pragma unroll
            for (int it = 0; it < 8; it++) {
                int chunk = tid + it*256;
                int r = chunk >> 4, c8 = (chunk & 15) << 3;   // 8 halfs per chunk
                cpasync16(dstb + (uint32_t)((r*LDS2 + c8) * 2), s + (size_t)r*Ee + c8);
            }
        }
        asm volatile("cp.async.commit_group;\n");
        asm volatile("cp.async.wait_group 0;\n");
    }
    __syncthreads();

    const int arow = lane & 15;
    const int acol = ((lane >> 4) & 1) * 8;
    const int brow = lane & 7;
    const int bcol = ((lane >> 3) & 1) * 8;
    const int vrow = lane & 15;       // trans-B: rows k..k+15

    float acc[16][4];

    // ---- Scores = Q K^T (3xBF16 split) ----
    #pragma unroll
    for (int j = 0; j < 16; j++) { acc[j][0]=0.f; acc[j][1]=0.f; acc[j][2]=0.f; acc[j][3]=0.f; }

    for (int kk = 0; kk < Dd; kk += 16) {
        uint32_t AH[4], AL[4];
        uint32_t aoff = (uint32_t)(((warp*16 + arow)*LDS2 + kk + acol) * 2);
        ldsm_x4(AH, smb + OFF_QH + aoff);
        ldsm_x4(AL, smb + OFF_QL + aoff);
        #pragma unroll
        for (int j = 0; j < 16; j++) {
            uint32_t BH[2], BL[2];
            uint32_t boff = (uint32_t)(((j*8 + brow)*LDS2 + kk + bcol) * 2);
            ldsm_x2(BH, smb + OFF_KH + boff);
            ldsm_x2(BL, smb + OFF_KL + boff);
            mma16(acc[j], AH, BH);
            mma16(acc[j], AH, BL);
            mma16(acc[j], AL, BH);
        }
    }
    // Store scores fp32
    #pragma unroll
    for (int j = 0; j < 16; j++) {
        float* p = sS + (warp*16 + g)*LDT + j*8 + 2*t;
        *(float2*)p           = { acc[j][0], acc[j][1] };
        *(float2*)(p + 8*LDT) = { acc[j][2], acc[j][3] };
    }
    __syncthreads();   // all QK^T smem reads done; Q/K buffers reusable

    // Kick off V loads into Q's buffers (overlaps softmax)
    {
        const uint16_t* s0 = vh + base;
        const uint16_t* s1 = vl + base;
        #pragma unroll
        for (int it = 0; it < 8; it++) {
            int chunk = tid + it*256;
            int r = chunk >> 4, c8 = (chunk & 15) << 3;
            uint32_t doff = (uint32_t)((r*LDS2 + c8) * 2);
            cpasync16(smb + OFF_QH + doff, s0 + (size_t)r*Ee + c8);
            cpasync16(smb + OFF_QL + doff, s1 + (size_t)r*Ee + c8);
        }
        asm volatile("cp.async.commit_group;\n");
    }

    // Row softmax (warp owns rows warp*16..+16)
    #pragma unroll 1
    for (int rr = 0; rr < 16; rr++) {
        float* row = sS + (warp*16 + rr)*LDT;
        float v0 = row[lane], v1 = row[lane+32], v2 = row[lane+64], v3 = row[lane+96];
        float m = fmaxf(fmaxf(v0, v1), fmaxf(v2, v3));
        #pragma unroll
        for (int off = 16; off > 0; off >>= 1)
            m = fmaxf(m, __shfl_xor_sync(0xFFFFFFFFu, m, off));
        v0 = __expf(v0 - m); v1 = __expf(v1 - m); v2 = __expf(v2 - m); v3 = __expf(v3 - m);
        float s = v0 + v1 + v2 + v3;
        #pragma unroll
        for (int off = 16; off > 0; off >>= 1)
            s += __shfl_xor_sync(0xFFFFFFFFu, s, off);
        float inv = 1.0f / s;
        row[lane]    = v0 * inv;
        row[lane+32] = v1 * inv;
        row[lane+64] = v2 * inv;
        row[lane+96] = v3 * inv;
    }

    // Split own P rows -> bf16 hi/lo (into former K buffers)
    #pragma unroll
    for (int rr = 0; rr < 16; rr++) {
        int row = warp*16 + rr;
        #pragma unroll
        for (int wi = 0; wi < 2; wi++) {
            int cw = lane + wi*32;           // word col 0..63
            float2 v = *(float2*)(sS + row*LDT + 2*cw);
            uint32_t hh, ll;
            split2(v.x, v.y, hh, ll);
            sPh[row*(LDS2/2) + cw] = hh;
            sPl[row*(LDS2/2) + cw] = ll;
        }
    }

    asm volatile("cp.async.wait_group 0;\n");
    __syncthreads();   // V landed + all P split

    // ---- Out = P V (3xBF16 split, trans-B from V[s][d]) ----
    #pragma unroll
    for (int j = 0; j < 16; j++) { acc[j][0]=0.f; acc[j][1]=0.f; acc[j][2]=0.f; acc[j][3]=0.f; }

    for (int kk = 0; kk < Ss; kk += 16) {
        uint32_t AH[4], AL[4];
        uint32_t aoff = (uint32_t)(((warp*16 + arow)*LDS2 + kk + acol) * 2);
        ldsm_x4(AH, smb + OFF_KH + aoff);   // P hi
        ldsm_x4(AL, smb + OFF_KL + aoff);   // P lo
        #pragma unroll
        for (int j = 0; j < 16; j++) {
            uint32_t BH[2], BL[2];
            uint32_t boff = (uint32_t)(((kk + vrow)*LDS2 + j*8) * 2);
            ldsm_x2t(BH, smb + OFF_QH + boff);   // V hi (trans)
            ldsm_x2t(BL, smb + OFF_QL + boff);   // V lo (trans)
            mma16(acc[j], AH, BH);
            mma16(acc[j], AH, BL);
            mma16(acc[j], AL, BH);
        }
    }

    // Epilogue: exact split -> att hi/lo
    #pragma unroll
    for (int j = 0; j < 16; j++) {
        size_t row = (size_t)(b*Ss + warp*16 + g);
        int colw = h*(Dd/2) + j*4 + t;
        uint32_t h0, l0, h1, l1;
        split2(acc[j][0], acc[j][1], h0, l0);
        split2(acc[j][2], acc[j][3], h1, l1);
        ath[row*(Ee/2) + colw]       = h0;
        atl[row*(Ee/2) + colw]       = l0;
        ath[(row + 8)*(Ee/2) + colw] = h1;
        atl[(row + 8)*(Ee/2) + colw] = l1;
    }
}

// ---------------- Launch ----------------
extern "C" void kernel_launch(void* const* d_in, const int* in_sizes, int n_in,
                              void* d_out, int out_size) {
    const float* x  = (const float*)d_in[0];
    const float* Wq = (const float*)d_in[1];
    const float* bq = (const float*)d_in[2];
    const float* Wk = (const float*)d_in[3];
    const float* bk = (const float*)d_in[4];
    const float* Wv = (const float*)d_in[5];
    const float* bv = (const float*)d_in[6];
    const float* Wo = (const float*)d_in[7];
    const float* bo = (const float*)d_in[8];
    float* y = (float*)d_out;

    uint32_t *qh, *ql, *kh, *kl, *vh, *vl, *ath, *atl, *wthO, *wtlO;
    cudaGetSymbolAddress((void**)&qh,  g_qh);
    cudaGetSymbolAddress((void**)&ql,  g_ql);
    cudaGetSymbolAddress((void**)&kh,  g_kh);
    cudaGetSymbolAddress((void**)&kl,  g_kl);
    cudaGetSymbolAddress((void**)&vh,  g_vh);
    cudaGetSymbolAddress((void**)&vl,  g_vl);
    cudaGetSymbolAddress((void**)&ath, g_ath);
    cudaGetSymbolAddress((void**)&atl, g_atl);
    cudaGetSymbolAddress((void**)&wthO, g_wthO);
    cudaGetSymbolAddress((void**)&wtlO, g_wtlO);

    cudaFuncSetAttribute(attn_kernel, cudaFuncAttributeMaxDynamicSharedMemorySize, ATTN_SMEM);
    cudaFuncSetAttribute(qkv_kernel,  cudaFuncAttributeMaxDynamicSharedMemorySize, GEMM_SMEM);
    cudaFuncSetAttribute(out_kernel,  cudaFuncAttributeMaxDynamicSharedMemorySize, BGEMM_SMEM);

    // Prepass: split Wo^T once
    dim3 cwg(Ee/32, Ee/2/32);
    dim3 cwb(32, 8);
    conv_w<<<cwg, cwb>>>(Wo, wthO, wtlO);

    dim3 gqkv(12, Mtot/128);
    qkv_kernel<<<gqkv, 256, GEMM_SMEM>>>(x, Wq, bq, Wk, bk, Wv, bv,
                                         qh, ql, kh, kl, vh, vl);

    attn_kernel<<<Bb*Hh, 256, ATTN_SMEM>>>((const uint16_t*)qh, (const uint16_t*)ql,
                                           (const uint16_t*)kh, (const uint16_t*)kl,
                                           (const uint16_t*)vh, (const uint16_t*)vl,
                                           ath, atl);

    dim3 gout(Ee/128, Mtot/128);
    out_kernel<<<gout, 256, BGEMM_SMEM>>>((const uint16_t*)ath, (const uint16_t*)atl,
                                          (const uint16_t*)wthO, (const uint16_t*)wtlO,
                                          bo, y);
}

// round 13
// speedup vs baseline: 1.2096x; 1.0417x over previous
#include <cuda_runtime.h>
#include <cstdint>

// Problem dims
#define Bb 384
#define Ss 128
#define Ee 512
#define Hh 4
#define Dd 128
#define Mtot (Bb*Ss)   // 49152

// Scratch (device globals; resolved via cudaGetSymbolAddress)
__device__ uint32_t g_qh[(size_t)Mtot*Ee/2];
__device__ uint32_t g_ql[(size_t)Mtot*Ee/2];
__device__ uint32_t g_kh[(size_t)Mtot*Ee/2];
__device__ uint32_t g_kl[(size_t)Mtot*Ee/2];
__device__ uint32_t g_vh[(size_t)Mtot*Ee/2];
__device__ uint32_t g_vl[(size_t)Mtot*Ee/2];
__device__ uint32_t g_ath[(size_t)Mtot*Ee/2];
__device__ uint32_t g_atl[(size_t)Mtot*Ee/2];
__device__ uint32_t g_wthO[(size_t)Ee*Ee/2];  // Wo^T hi [N][K]
__device__ uint32_t g_wtlO[(size_t)Ee*Ee/2];  // Wo^T lo

// ---------------- PTX helpers ----------------
__device__ __forceinline__ void mma16(float* c, const uint32_t* a, const uint32_t* b) {
    asm volatile(
        "mma.sync.aligned.m16n8k16.row.col.f32.bf16.bf16.f32 "
        "{%0,%1,%2,%3}, {%4,%5,%6,%7}, {%8,%9}, {%0,%1,%2,%3};\n"
        : "+f"(c[0]), "+f"(c[1]), "+f"(c[2]), "+f"(c[3])
        : "r"(a[0]), "r"(a[1]), "r"(a[2]), "r"(a[3]), "r"(b[0]), "r"(b[1]));
}
__device__ __forceinline__ void ldsm_x4(uint32_t* r, uint32_t saddr) {
    asm volatile("ldmatrix.sync.aligned.m8n8.x4.shared.b16 {%0,%1,%2,%3}, [%4];\n"
        : "=r"(r[0]), "=r"(r[1]), "=r"(r[2]), "=r"(r[3]) : "r"(saddr));
}
__device__ __forceinline__ void ldsm_x2(uint32_t* r, uint32_t saddr) {
    asm volatile("ldmatrix.sync.aligned.m8n8.x2.shared.b16 {%0,%1}, [%2];\n"
        : "=r"(r[0]), "=r"(r[1]) : "r"(saddr));
}
__device__ __forceinline__ void ldsm_x2t(uint32_t* r, uint32_t saddr) {
    asm volatile("ldmatrix.sync.aligned.m8n8.x2.trans.shared.b16 {%0,%1}, [%2];\n"
        : "=r"(r[0]), "=r"(r[1]) : "r"(saddr));
}
// Split (x0,x1) -> packed bf16x2 hi (rn) + packed bf16x2 lo residual.
__device__ __forceinline__ void split2(float x0, float x1, uint32_t& hi, uint32_t& lo) {
    asm("cvt.rn.bf16x2.f32 %0, %1, %2;" : "=r"(hi) : "f"(x1), "f"(x0));
    float r0 = x0 - __uint_as_float(hi << 16);
    float r1 = x1 - __uint_as_float(hi & 0xFFFF0000u);
    asm("cvt.rn.bf16x2.f32 %0, %1, %2;" : "=r"(lo) : "f"(r1), "f"(r0));
}
__device__ __forceinline__ uint32_t smem_u32(const void* p) {
    return (uint32_t)__cvta_generic_to_shared(p);
}
__device__ __forceinline__ void cpasync16(uint32_t dst_smem, const void* src) {
    asm volatile("cp.async.cg.shared.global [%0], [%1], 16;\n" :: "r"(dst_smem), "l"(src));
}

// ---------------- Prepass: Wo [K][N] -> Wo^T hi/lo [N][K], coalesced ----------------
__global__ __launch_bounds__(256) void conv_w(const float* __restrict__ W,
                                              uint32_t* __restrict__ wh,
                                              uint32_t* __restrict__ wl) {
    __shared__ uint32_t sh[32][33], sl[32][33];
    const int tx = threadIdx.x, ty = threadIdx.y;
    const int n0 = blockIdx.x * 32, kw0 = blockIdx.y * 32;
    #pragma unroll
    for (int dy = 0; dy < 32; dy += 8) {
        int kw = kw0 + ty + dy;
        float a = W[(size_t)(2*kw  )*Ee + n0 + tx];
        float b = W[(size_t)(2*kw+1)*Ee + n0 + tx];
        uint32_t h, l; split2(a, b, h, l);
        sh[ty+dy][tx] = h; sl[ty+dy][tx] = l;
    }
    __syncthreads();
    #pragma unroll
    for (int dy = 0; dy < 32; dy += 8) {
        int n = n0 + ty + dy;
        wh[(size_t)n*(Ee/2) + kw0 + tx] = sh[tx][ty+dy];
        wl[(size_t)n*(Ee/2) + kw0 + tx] = sl[tx][ty+dy];
    }
}

// =========== QKV GEMM (convert-in-kernel; term-pass reordered mma) ===========
#define LDA 36
#define LDB 132
#define ASTG (128*LDA)
#define WSTG (32*LDB)
#define LDH  20
#define HTW  (128*LDH)
#define AHIW (2*ASTG + 2*WSTG)
#define ALOW (AHIW + HTW)
#define WTHI (ALOW + HTW)
#define WTLO (WTHI + HTW)
#define GEMM_SMEM ((WTLO + HTW) * 4)   // 111616 bytes

__device__ __forceinline__ void gemm_body(const float* __restrict__ A,
                                          const float* __restrict__ W,
                                          const float* __restrict__ bias,
                                          uint32_t* __restrict__ Ch,
                                          uint32_t* __restrict__ Cl,
                                          int bm, int bn, float* smem) {
    float* Asm = smem;
    float* Wsm = smem + 2*ASTG;
    uint32_t* ah_w = (uint32_t*)(smem + AHIW);
    uint32_t* al_w = (uint32_t*)(smem + ALOW);
    uint32_t* wh_w = (uint32_t*)(smem + WTHI);
    uint32_t* wl_w = (uint32_t*)(smem + WTLO);

    const int tid  = threadIdx.x;
    const int warp = tid >> 5;
    const int lane = tid & 31;
    const int g = lane >> 2, t = lane & 3;
    const int wm = (warp >> 1) * 32;
    const int wn = (warp & 1) * 64;

    const int ar = tid >> 3, ac = (tid & 7) << 2;
    const int wr = tid >> 5, wc = (tid & 31) << 2;

    const int arow = lane & 15;
    const int acol = ((lane >> 4) & 1) * 8;
    const int brow = lane & 7;
    const int bcol = ((lane >> 3) & 1) * 8;

    const uint32_t ah_b = smem_u32(ah_w);
    const uint32_t al_b = smem_u32(al_w);
    const uint32_t wh_b = smem_u32(wh_w);
    const uint32_t wl_b = smem_u32(wl_w);

    float acc[2][8][4] = {};

    #define ISSUE(k0, s)  do {                                                  \
        float* as_ = Asm + (s)*ASTG;                                            \
        float* ws_ = Wsm + (s)*WSTG;                                            \
        _Pragma("unroll")                                                       \
        for (int it = 0; it < 4; it++)                                          \
            cpasync16(smem_u32(as_ + (ar + it*32)*LDA + ac),                    \
                      A + (size_t)(bm + ar + it*32)*Ee + (k0) + ac);            \
        _Pragma("unroll")                                                       \
        for (int it = 0; it < 4; it++)                                          \
            cpasync16(smem_u32(ws_ + (wr + it*8)*LDB + wc),                     \
                      W + (size_t)((k0) + wr + it*8)*Ee + bn + wc);             \
        asm volatile("cp.async.commit_group;\n");                               \
    } while (0)

    ISSUE(0, 0);

    for (int ki = 0; ki < Ee/32; ki++) {
        if (ki + 1 < Ee/32) {
            ISSUE((ki+1)*32, (ki+1) & 1);
            asm volatile("cp.async.wait_group 1;\n");
        } else {
            asm volatile("cp.async.wait_group 0;\n");
        }
        __syncthreads();

        const float* as_ = Asm + (ki & 1)*ASTG;
        const float* ws_ = Wsm + (ki & 1)*WSTG;

        // convert A tile fp32 -> bf16 hi/lo
        #pragma unroll
        for (int it = 0; it < 4; it++) {
            int r = ar + it*32;
            float4 v = *(const float4*)(as_ + r*LDA + ac);
            uint32_t h0, l0, h1, l1;
            split2(v.x, v.y, h0, l0);
            split2(v.z, v.w, h1, l1);
            int o = r*LDH + (ac >> 1);
            ah_w[o] = h0; ah_w[o+1] = h1;
            al_w[o] = l0; al_w[o+1] = l1;
        }
        // convert W tile fp32 [k][n] -> transposed bf16 hi/lo [n][k]
        #pragma unroll
        for (int it = 0; it < 4; it++) {
            int unit = tid + it*256;
            int n = unit & 127, k0 = (unit >> 7) << 2;
            float c0 = ws_[(k0  )*LDB + n];
            float c1 = ws_[(k0+1)*LDB + n];
            float c2 = ws_[(k0+2)*LDB + n];
            float c3 = ws_[(k0+3)*LDB + n];
            uint32_t h0, l0, h1, l1;
            split2(c0, c1, h0, l0);
            split2(c2, c3, h1, l1);
            int o = n*LDH + (k0 >> 1);
            wh_w[o] = h0; wh_w[o+1] = h1;
            wl_w[o] = l0; wl_w[o+1] = l1;
        }
        __syncthreads();

        // ---- mma: term-pass reordering for max accumulator dependency distance ----
        #pragma unroll
        for (int kk = 0; kk < 32; kk += 16) {
            uint32_t AH[2][4], AL[2][4];
            #pragma unroll
            for (int i = 0; i < 2; i++) {
                uint32_t off = (uint32_t)(((wm + i*16 + arow)*40 + kk + acol) * 2);
                ldsm_x4(AH[i], ah_b + off);
                ldsm_x4(AL[i], al_b + off);
            }
            uint32_t BH[8][2];
            #pragma unroll
            for (int j = 0; j < 8; j++) {
                uint32_t off = (uint32_t)(((wn + j*8 + brow)*40 + kk + bcol) * 2);
                ldsm_x2(BH[j], wh_b + off);
            }
            // pass 1: AH * BH
            #pragma unroll
            for (int j = 0; j < 8; j++) {
                mma16(acc[0][j], AH[0], BH[j]);
                mma16(acc[1][j], AH[1], BH[j]);
            }
            // pass 2: AH * BL (double-buffered ldsm, one j ahead)
            uint32_t BLb[2][2];
            {
                uint32_t off0 = (uint32_t)(((wn + brow)*40 + kk + bcol) * 2);
                ldsm_x2(BLb[0], wl_b + off0);
            }
            #pragma unroll
            for (int j = 0; j < 8; j++) {
                if (j < 7) {
                    uint32_t offn = (uint32_t)(((wn + (j+1)*8 + brow)*40 + kk + bcol) * 2);
                    ldsm_x2(BLb[(j+1)&1], wl_b + offn);
                }
                mma16(acc[0][j], AH[0], BLb[j&1]);
                mma16(acc[1][j], AH[1], BLb[j&1]);
            }
            // pass 3: AL * BH
            #pragma unroll
            for (int j = 0; j < 8; j++) {
                mma16(acc[0][j], AL[0], BH[j]);
                mma16(acc[1][j], AL[1], BH[j]);
            }
        }
    }
    #undef ISSUE

    // Epilogue: bias + exact split -> bf16 hi/lo outputs
    #pragma unroll
    for (int i = 0; i < 2; i++) {
        #pragma unroll
        for (int j = 0; j < 8; j++) {
            int row  = bm + wm + i*16 + g;
            int col  = bn + wn + j*8 + 2*t;
            int colw = col >> 1;
            float bz0 = bias[col], bz1 = bias[col+1];
            uint32_t h0, l0, h1, l1;
            split2(acc[i][j][0] + bz0, acc[i][j][1] + bz1, h0, l0);
            split2(acc[i][j][2] + bz0, acc[i][j][3] + bz1, h1, l1);
            Ch[(size_t)row*(Ee/2) + colw]       = h0;
            Cl[(size_t)row*(Ee/2) + colw]       = l0;
            Ch[(size_t)(row + 8)*(Ee/2) + colw] = h1;
            Cl[(size_t)(row + 8)*(Ee/2) + colw] = l1;
        }
    }
}

__global__ __launch_bounds__(256, 2) void qkv_kernel(const float* __restrict__ x,
        const float* __restrict__ Wq, const float* __restrict__ bq,
        const float* __restrict__ Wk, const float* __restrict__ bk,
        const float* __restrict__ Wv, const float* __restrict__ bv,
        uint32_t* __restrict__ qh, uint32_t* __restrict__ ql,
        uint32_t* __restrict__ kh, uint32_t* __restrict__ kl,
        uint32_t* __restrict__ vh, uint32_t* __restrict__ vl) {
    extern __shared__ float smem[];
    const int mat = blockIdx.x % 3;
    const int bn  = (blockIdx.x / 3) * 128;
    const int bm  = blockIdx.y * 128;
    const float* W; const float* bias; uint32_t* Ch; uint32_t* Cl;
    if (mat == 0)      { W = Wq; bias = bq; Ch = qh; Cl = ql; }
    else if (mat == 1) { W = Wk; bias = bk; Ch = kh; Cl = kl; }
    else               { W = Wv; bias = bv; Ch = vh; Cl = vl; }
    gemm_body(x, W, bias, Ch, Cl, bm, bn, smem);
}

// =========== Output GEMM (pure bf16; term-pass reordered) ===========
#define LDHW 20
#define TILEW (128*LDHW)
#define STGW  (4*TILEW)
#define BGEMM_SMEM (2*STGW*4)   // 81920 bytes

__global__ __launch_bounds__(256, 2) void out_kernel(
        const uint16_t* __restrict__ Ah16, const uint16_t* __restrict__ Al16,
        const uint16_t* __restrict__ Bh16, const uint16_t* __restrict__ Bl16,
        const float* __restrict__ bias, float* __restrict__ C) {
    extern __shared__ uint32_t smw[];
    const int bm = blockIdx.y * 128;
    const int bn = blockIdx.x * 128;

    const int tid  = threadIdx.x;
    const int warp = tid >> 5;
    const int lane = tid & 31;
    const int g = lane >> 2, t = lane & 3;
    const int wm = (warp >> 1) * 32;
    const int wn = (warp & 1) * 64;

    const int cr = tid >> 2;
    const int cc = (tid & 3) << 3;

    const int arow = lane & 15;
    const int acol = ((lane >> 4) & 1) * 8;
    const int brow = lane & 7;
    const int bcol = ((lane >> 3) & 1) * 8;

    const uint32_t smb = smem_u32(smw);

    float acc[2][8][4] = {};

    #define OISSUE(k0, s)  do {                                                   \
        uint32_t* st = smw + (s)*STGW;                                            \
        _Pragma("unroll")                                                         \
        for (int it = 0; it < 2; it++) {                                          \
            int r = cr + it*64;                                                   \
            int dof = r*LDHW + (cc >> 1);                                         \
            cpasync16(smem_u32(st + 0*TILEW + dof), Ah16 + (size_t)(bm + r)*Ee + (k0) + cc);\
            cpasync16(smem_u32(st + 1*TILEW + dof), Al16 + (size_t)(bm + r)*Ee + (k0) + cc);\
            cpasync16(smem_u32(st + 2*TILEW + dof), Bh16 + (size_t)(bn + r)*Ee + (k0) + cc);\
            cpasync16(smem_u32(st + 3*TILEW + dof), Bl16 + (size_t)(bn + r)*Ee + (k0) + cc);\
        }                                                                         \
        asm volatile("cp.async.commit_group;\n");                                 \
    } while (0)

    OISSUE(0, 0);

    for (int ki = 0; ki < Ee/32; ki++) {
        if (ki + 1 < Ee/32) {
            OISSUE((ki+1)*32, (ki+1) & 1);
            asm volatile("cp.async.wait_group 1;\n");
        } else {
            asm volatile("cp.async.wait_group 0;\n");
        }
        __syncthreads();

        const uint32_t base = smb + (uint32_t)((ki & 1)*STGW*4);

        #pragma unroll
        for (int kk = 0; kk < 32; kk += 16) {
            uint32_t AH[2][4], AL[2][4];
            #pragma unroll
            for (int i = 0; i < 2; i++) {
                uint32_t off = (uint32_t)(((wm + i*16 + arow)*40 + kk + acol) * 2);
                ldsm_x4(AH[i], base + 0*TILEW*4 + off);
                ldsm_x4(AL[i], base + 1*TILEW*4 + off);
            }
            uint32_t BH[8][2];
            #pragma unroll
            for (int j = 0; j < 8; j++) {
                uint32_t off = (uint32_t)(((wn + j*8 + brow)*40 + kk + bcol) * 2);
                ldsm_x2(BH[j], base + 2*TILEW*4 + off);
            }
            #pragma unroll
            for (int j = 0; j < 8; j++) {
                mma16(acc[0][j], AH[0], BH[j]);
                mma16(acc[1][j], AH[1], BH[j]);
            }
            uint32_t BLb[2][2];
            {
                uint32_t off0 = (uint32_t)(((wn + brow)*40 + kk + bcol) * 2);
                ldsm_x2(BLb[0], base + 3*TILEW*4 + off0);
            }
            #pragma unroll
            for (int j = 0; j < 8; j++) {
                if (j < 7) {
                    uint32_t offn = (uint32_t)(((wn + (j+1)*8 + brow)*40 + kk + bcol) * 2);
                    ldsm_x2(BLb[(j+1)&1], base + 3*TILEW*4 + offn);
                }
                mma16(acc[0][j], AH[0], BLb[j&1]);
                mma16(acc[1][j], AH[1], BLb[j&1]);
            }
            #pragma unroll
            for (int j = 0; j < 8; j++) {
                mma16(acc[0][j], AL[0], BH[j]);
                mma16(acc[1][j], AL[1], BH[j]);
            }
        }
        __syncthreads();
    }
    #undef OISSUE

    #pragma unroll
    for (int i = 0; i < 2; i++) {
        #pragma unroll
        for (int j = 0; j < 8; j++) {
            int row = bm + wm + i*16 + g;
            int col = bn + wn + j*8 + 2*t;
            float bz0 = bias[col], bz1 = bias[col+1];
            float2 v0 = { acc[i][j][0] + bz0, acc[i][j][1] + bz1 };
            float2 v1 = { acc[i][j][2] + bz0, acc[i][j][3] + bz1 };
            *(float2*)(C + (size_t)row*Ee + col)       = v0;
            *(float2*)(C + (size_t)(row + 8)*Ee + col) = v1;
        }
    }
}

// =========== Attention: register-resident flash, bf16 split ===========
// smem = 6 bf16 tiles (Qh Ql Kh Kl Vh Vl), no score/P smem at all.
#define LDS2 136
#define T2B  (128*LDS2*2)              // 34816 B per tile
#define OFF_QH 0
#define OFF_QL (T2B)
#define OFF_KH (2*T2B)
#define OFF_KL (3*T2B)
#define OFF_VH (4*T2B)
#define OFF_VL (5*T2B)
#define ATTN_SMEM (6*T2B)              // 208896 bytes

__global__ __launch_bounds__(256) void attn_kernel(
        const uint16_t* __restrict__ qh, const uint16_t* __restrict__ ql,
        const uint16_t* __restrict__ kh, const uint16_t* __restrict__ kl,
        const uint16_t* __restrict__ vh, const uint16_t* __restrict__ vl,
        uint32_t* __restrict__ ath, uint32_t* __restrict__ atl) {
    extern __shared__ char sm[];
    const uint32_t smb = smem_u32(sm);

    const int bh = blockIdx.x;
    const int b  = bh >> 2;
    const int h  = bh & 3;
    const int tid  = threadIdx.x;
    const int warp = tid >> 5;
    const int lane = tid & 31;
    const int g = lane >> 2, t = lane & 3;

    const size_t base = (size_t)(b*Ss)*Ee + h*Dd;   // halfs

    // group 1: Q,K tiles; group 2: V tiles (overlaps QK^T)
    {
        const uint16_t* srcs[4] = { qh, ql, kh, kl };
        #pragma unroll
        for (int tile = 0; tile < 4; tile++) {
            const uint16_t* s = srcs[tile] + base;
            uint32_t dstb = smb + tile*T2B;
            #pragma unroll
            for (int it = 0; it < 8; it++) {
                int chunk = tid + it*256;
                int r = chunk >> 4, c8 = (chunk & 15) << 3;
                cpasync16(dstb + (uint32_t)((r*LDS2 + c8) * 2), s + (size_t)r*Ee + c8);
            }
        }
        asm volatile("cp.async.commit_group;\n");
        const uint16_t* s0 = vh + base;
        const uint16_t* s1 = vl + base;
        #pragma unroll
        for (int it = 0; it < 8; it++) {
            int chunk = tid + it*256;
            int r = chunk >> 4, c8 = (chunk & 15) << 3;
            uint32_t doff = (uint32_t)((r*LDS2 + c8) * 2);
            cpasync16(smb + OFF_VH + doff, s0 + (size_t)r*Ee + c8);
            cpasync16(smb + OFF_VL + doff, s1 + (size_t)r*Ee + c8);
        }
        asm volatile("cp.async.commit_group;\n");
        asm volatile("cp.async.wait_group 1;\n");   // Q,K landed; V in flight
    }
    __syncthreads();

    const int arow = lane & 15;
    const int acol = ((lane >> 4) & 1) * 8;
    const int brow = lane & 7;
    const int bcol = ((lane >> 3) & 1) * 8;
    const int vrow = lane & 15;

    // ---- Scores = Q K^T (3xBF16 split, chunk-8 term passes) ----
    float acc[16][4];
    #pragma unroll
    for (int j = 0; j < 16; j++) { acc[j][0]=0.f; acc[j][1]=0.f; acc[j][2]=0.f; acc[j][3]=0.f; }

    for (int kk = 0; kk < Dd; kk += 16) {
        uint32_t AH[4], AL[4];
        uint32_t aoff = (uint32_t)(((warp*16 + arow)*LDS2 + kk + acol) * 2);
        ldsm_x4(AH, smb + OFF_QH + aoff);
        ldsm_x4(AL, smb + OFF_QL + aoff);
        #pragma unroll
        for (int jc = 0; jc < 16; jc += 8) {
            uint32_t BH[8][2], BL[8][2];
            #pragma unroll
            for (int j2 = 0; j2 < 8; j2++) {
                uint32_t boff = (uint32_t)((((jc+j2)*8 + brow)*LDS2 + kk + bcol) * 2);
                ldsm_x2(BH[j2], smb + OFF_KH + boff);
                ldsm_x2(BL[j2], smb + OFF_KL + boff);
            }
            #pragma unroll
            for (int j2 = 0; j2 < 8; j2++) mma16(acc[jc+j2], AH, BH[j2]);
            #pragma unroll
            for (int j2 = 0; j2 < 8; j2++) mma16(acc[jc+j2], AH, BL[j2]);
            #pragma unroll
            for (int j2 = 0; j2 < 8; j2++) mma16(acc[jc+j2], AL, BH[j2]);
        }
    }

    // ---- Register softmax ----
    // Row r=g: acc[j][0..1] over j; row r=g+8: acc[j][2..3]. Quad lanes (same g,
    // t=0..3) are consecutive lanes -> shfl_xor 1,2 completes the row reduction.
    float m0 = -1e30f, m1 = -1e30f;
    #pragma unroll
    for (int j = 0; j < 16; j++) {
        m0 = fmaxf(m0, fmaxf(acc[j][0], acc[j][1]));
        m1 = fmaxf(m1, fmaxf(acc[j][2], acc[j][3]));
    }
    m0 = fmaxf(m0, __shfl_xor_sync(0xFFFFFFFFu, m0, 1));
    m0 = fmaxf(m0, __shfl_xor_sync(0xFFFFFFFFu, m0, 2));
    m1 = fmaxf(m1, __shfl_xor_sync(0xFFFFFFFFu, m1, 1));
    m1 = fmaxf(m1, __shfl_xor_sync(0xFFFFFFFFu, m1, 2));
    float s0 = 0.f, s1 = 0.f;
    #pragma unroll
    for (int j = 0; j < 16; j++) {
        acc[j][0] = __expf(acc[j][0] - m0);
        acc[j][1] = __expf(acc[j][1] - m0);
        acc[j][2] = __expf(acc[j][2] - m1);
        acc[j][3] = __expf(acc[j][3] - m1);
        s0 += acc[j][0] + acc[j][1];
        s1 += acc[j][2] + acc[j][3];
    }
    s0 += __shfl_xor_sync(0xFFFFFFFFu, s0, 1);
    s0 += __shfl_xor_sync(0xFFFFFFFFu, s0, 2);
    s1 += __shfl_xor_sync(0xFFFFFFFFu, s1, 1);
    s1 += __shfl_xor_sync(0xFFFFFFFFu, s1, 2);
    float inv0 = 1.0f / s0, inv1 = 1.0f / s1;

    // ---- Pack P directly into A-operand frags (exact bf16 hi/lo split) ----
    // A frag (m16n8k16) for k-slice k0: a0=(g,2t,2t+1)=acc[2k0][0..1],
    // a1=(g+8,..)=acc[2k0][2..3], a2=(g,8+2t)=acc[2k0+1][0..1], a3=acc[2k0+1][2..3].
    uint32_t PH[8][4], PL[8][4];
    #pragma unroll
    for (int k0 = 0; k0 < 8; k0++) {
        split2(acc[2*k0][0]*inv0,   acc[2*k0][1]*inv0,   PH[k0][0], PL[k0][0]);
        split2(acc[2*k0][2]*inv1,   acc[2*k0][3]*inv1,   PH[k0][1], PL[k0][1]);
        split2(acc[2*k0+1][0]*inv0, acc[2*k0+1][1]*inv0, PH[k0][2], PL[k0][2]);
        split2(acc[2*k0+1][2]*inv1, acc[2*k0+1][3]*inv1, PH[k0][3], PL[k0][3]);
    }

    asm volatile("cp.async.wait_group 0;\n");   // V landed
    __syncthreads();

    // ---- Out = P V (trans-B from V[s][d], chunk-8 term passes) ----
    float oacc[16][4];
    #pragma unroll
    for (int j = 0; j < 16; j++) { oacc[j][0]=0.f; oacc[j][1]=0.f; oacc[j][2]=0.f; oacc[j][3]=0.f; }

    for (int kk = 0; kk < Ss; kk += 16) {
        const int k0 = kk >> 4;
        #pragma unroll
        for (int jc = 0; jc < 16; jc += 8) {
            uint32_t VH[8][2], VL[8][2];
            #pragma unroll
            for (int j2 = 0; j2 < 8; j2++) {
                uint32_t boff = (uint32_t)(((kk + vrow)*LDS2 + (jc+j2)*8) * 2);
                ldsm_x2t(VH[j2], smb + OFF_VH + boff);
                ldsm_x2t(VL[j2], smb + OFF_VL + boff);
            }
            #pragma unroll
            for (int j2 = 0; j2 < 8; j2++) mma16(oacc[jc+j2], PH[k0], VH[j2]);
            #pragma unroll
            for (int j2 = 0; j2 < 8; j2++) mma16(oacc[jc+j2], PH[k0], VL[j2]);
            #pragma unroll
            for (int j2 = 0; j2 < 8; j2++) mma16(oacc[jc+j2], PL[k0], VH[j2]);
        }
    }

    // Epilogue: exact split -> att hi/lo
    #pragma unroll
    for (int j = 0; j < 16; j++) {
        size_t row = (size_t)(b*Ss + warp*16 + g);
        int colw = h*(Dd/2) + j*4 + t;
        uint32_t h0, l0, h1, l1;
        split2(oacc[j][0], oacc[j][1], h0, l0);
        split2(oacc[j][2], oacc[j][3], h1, l1);
        ath[row*(Ee/2) + colw]       = h0;
        atl[row*(Ee/2) + colw]       = l0;
        ath[(row + 8)*(Ee/2) + colw] = h1;
        atl[(row + 8)*(Ee/2) + colw] = l1;
    }
}

// ---------------- Launch ----------------
extern "C" void kernel_launch(void* const* d_in, const int* in_sizes, int n_in,
                              void* d_out, int out_size) {
    const float* x  = (const float*)d_in[0];
    const float* Wq = (const float*)d_in[1];
    const float* bq = (const float*)d_in[2];
    const float* Wk = (const float*)d_in[3];
    const float* bk = (const float*)d_in[4];
    const float* Wv = (const float*)d_in[5];
    const float* bv = (const float*)d_in[6];
    const float* Wo = (const float*)d_in[7];
    const float* bo = (const float*)d_in[8];
    float* y = (float*)d_out;

    uint32_t *qh, *ql, *kh, *kl, *vh, *vl, *ath, *atl, *wthO, *wtlO;
    cudaGetSymbolAddress((void**)&qh,  g_qh);
    cudaGetSymbolAddress((void**)&ql,  g_ql);
    cudaGetSymbolAddress((void**)&kh,  g_kh);
    cudaGetSymbolAddress((void**)&kl,  g_kl);
    cudaGetSymbolAddress((void**)&vh,  g_vh);
    cudaGetSymbolAddress((void**)&vl,  g_vl);
    cudaGetSymbolAddress((void**)&ath, g_ath);
    cudaGetSymbolAddress((void**)&atl, g_atl);
    cudaGetSymbolAddress((void**)&wthO, g_wthO);
    cudaGetSymbolAddress((void**)&wtlO, g_wtlO);

    cudaFuncSetAttribute(attn_kernel, cudaFuncAttributeMaxDynamicSharedMemorySize, ATTN_SMEM);
    cudaFuncSetAttribute(qkv_kernel,  cudaFuncAttributeMaxDynamicSharedMemorySize, GEMM_SMEM);
    cudaFuncSetAttribute(out_kernel,  cudaFuncAttributeMaxDynamicSharedMemorySize, BGEMM_SMEM);

    dim3 cwg(Ee/32, Ee/2/32);
    dim3 cwb(32, 8);
    conv_w<<<cwg, cwb>>>(Wo, wthO, wtlO);

    dim3 gqkv(12, Mtot/128);
    qkv_kernel<<<gqkv, 256, GEMM_SMEM>>>(x, Wq, bq, Wk, bk, Wv, bv,
                                         qh, ql, kh, kl, vh, vl);

    attn_kernel<<<Bb*Hh, 256, ATTN_SMEM>>>((const uint16_t*)qh, (const uint16_t*)ql,
                                           (const uint16_t*)kh, (const uint16_t*)kl,
                                           (const uint16_t*)vh, (const uint16_t*)vl,
                                           ath, atl);

    dim3 gout(Ee/128, Mtot/128);
    out_kernel<<<gout, 256, BGEMM_SMEM>>>((const uint16_t*)ath, (const uint16_t*)atl,
                                          (const uint16_t*)wthO, (const uint16_t*)wtlO,
                                          bo, y);
}